// round 2
// baseline (speedup 1.0000x reference)
#include <cuda_runtime.h>

#define B_   32
#define C_   3
#define H_   512
#define W_   512
#define HW_  (H_ * W_)
#define ROWS 32
#define HB_  (H_ / ROWS)          // 16 row-bands per image
#define NBLK (B_ * HB_)           // 512 blocks
#define TPB  256
#define TROWS (ROWS + 2)          // 34 tile rows (with halo)
#define STR  516                  // smem row stride (W+2 padded to 516)
#define SMEM_BYTES (TROWS * STR * 4)   // 70176 B (dynamic)

__device__ float g_partials[NBLK];
__device__ unsigned int g_count = 0;

__global__ __launch_bounds__(TPB) void edge_loss_kernel(
    const float* __restrict__ sr, const float* __restrict__ hr,
    float* __restrict__ out)
{
    extern __shared__ float g[];

    const int tid = threadIdx.x;
    const int b  = blockIdx.x / HB_;
    const int r0 = (blockIdx.x % HB_) * ROWS;

    const float* srb = sr + (size_t)b * C_ * HW_;
    const float* hrb = hr + (size_t)b * C_ * HW_;

    // Zero the left/right padding columns (cols 0 and W+1 = 513)
    if (tid < 2 * TROWS) {
        int tr  = tid >> 1;
        int col = (tid & 1) ? (W_ + 1) : 0;
        g[tr * STR + col] = 0.0f;
    }

    // Load halo'd gray-diff tile: 34 rows x 128 float4-chunks = 4352 tasks, 17/thread
    #pragma unroll
    for (int it = 0; it < (TROWS * (W_ / 4)) / TPB; ++it) {
        int idx   = tid + it * TPB;
        int tr    = idx >> 7;          // / 128
        int chunk = idx & 127;
        int gr    = r0 + tr - 1;

        float4 d = make_float4(0.f, 0.f, 0.f, 0.f);
        if (gr >= 0 && gr < H_) {
            size_t off = (size_t)gr * W_ + chunk * 4;
            float4 s0 = *(const float4*)(srb + 0 * HW_ + off);
            float4 s1 = *(const float4*)(srb + 1 * HW_ + off);
            float4 s2 = *(const float4*)(srb + 2 * HW_ + off);
            float4 h0 = *(const float4*)(hrb + 0 * HW_ + off);
            float4 h1 = *(const float4*)(hrb + 1 * HW_ + off);
            float4 h2 = *(const float4*)(hrb + 2 * HW_ + off);
            d.x = 0.2989f * (s0.x - h0.x) + 0.587f * (s1.x - h1.x) + 0.114f * (s2.x - h2.x);
            d.y = 0.2989f * (s0.y - h0.y) + 0.587f * (s1.y - h1.y) + 0.114f * (s2.y - h2.y);
            d.z = 0.2989f * (s0.z - h0.z) + 0.587f * (s1.z - h1.z) + 0.114f * (s2.z - h2.z);
            d.w = 0.2989f * (s0.w - h0.w) + 0.587f * (s1.w - h1.w) + 0.114f * (s2.w - h2.w);
        }
        float* dst = g + tr * STR + 1 + chunk * 4;
        dst[0] = d.x; dst[1] = d.y; dst[2] = d.z; dst[3] = d.w;
    }
    __syncthreads();

    // Sobel + abs + accumulate: 32 rows x 512 cols = 16384 pixels, 64/thread
    float acc = 0.0f;
    #pragma unroll 4
    for (int it = 0; it < (ROWS * W_) / TPB; ++it) {
        int idx = tid + it * TPB;
        int rr  = idx >> 9;            // / 512  -> 0..31
        int c   = idx & 511;
        const float* p = g + rr * STR + c;   // top-left of 3x3 neighborhood
        float a00 = p[0],           a01 = p[1],           a02 = p[2];
        float a10 = p[STR],                               a12 = p[STR + 2];
        float a20 = p[2 * STR],     a21 = p[2 * STR + 1], a22 = p[2 * STR + 2];
        float gx = (a00 - a02) + 2.0f * (a10 - a12) + (a20 - a22);
        float gy = (a00 - a20) + 2.0f * (a01 - a21) + (a02 - a22);
        acc += fabsf(gx) + fabsf(gy);
    }

    // Block reduce to one partial
    #pragma unroll
    for (int off = 16; off > 0; off >>= 1)
        acc += __shfl_xor_sync(0xFFFFFFFFu, acc, off);

    __shared__ float wsum[TPB / 32];
    __shared__ bool s_last;
    if ((tid & 31) == 0) wsum[tid >> 5] = acc;
    __syncthreads();
    if (tid == 0) {
        float s = 0.0f;
        #pragma unroll
        for (int w = 0; w < TPB / 32; ++w) s += wsum[w];
        g_partials[blockIdx.x] = s;
        __threadfence();
        unsigned int prev = atomicAdd(&g_count, 1u);
        s_last = (prev == NBLK - 1);
    }
    __syncthreads();

    // Last block folds the final reduction (no second kernel launch)
    if (s_last) {
        double a = 0.0;
        for (int i = tid; i < NBLK; i += TPB) a += (double)g_partials[i];
        double* sd = (double*)g;   // reuse tile smem
        sd[tid] = a;
        __syncthreads();
        #pragma unroll
        for (int off = TPB / 2; off > 0; off >>= 1) {
            if (tid < off) sd[tid] += sd[tid + off];
            __syncthreads();
        }
        if (tid == 0) {
            out[0] = (float)(sd[0] / (double)(B_ * (size_t)HW_));
            g_count = 0;   // reset for next replay (deterministic)
        }
    }
}

extern "C" void kernel_launch(void* const* d_in, const int* in_sizes, int n_in,
                              void* d_out, int out_size)
{
    const float* sr = (const float*)d_in[0];
    const float* hr = (const float*)d_in[1];
    float* out = (float*)d_out;

    cudaFuncSetAttribute(edge_loss_kernel,
                         cudaFuncAttributeMaxDynamicSharedMemorySize, SMEM_BYTES);
    edge_loss_kernel<<<NBLK, TPB, SMEM_BYTES>>>(sr, hr, out);
}

// round 3
// speedup vs baseline: 1.0006x; 1.0006x over previous
#include <cuda_runtime.h>

#define B_   32
#define C_   3
#define H_   512
#define W_   512
#define HW_  (H_ * W_)
#define ROWS 32
#define HB_  (H_ / ROWS)          // 16 row-bands per image
#define NBLK (B_ * HB_)           // 512 blocks
#define TPB  256
#define TROWS (ROWS + 2)          // 34 tile rows (with halo)
#define STR  516                  // smem row stride (W+2 padded to 516)
#define SMEM_BYTES (TROWS * STR * 4)   // 70176 B (dynamic)

__device__ float g_partials[NBLK];
__device__ unsigned int g_count = 0;

__global__ __launch_bounds__(TPB) void edge_loss_kernel(
    const float* __restrict__ sr, const float* __restrict__ hr,
    float* __restrict__ out)
{
    extern __shared__ float g[];

    const int tid = threadIdx.x;
    const int b  = blockIdx.x / HB_;
    const int r0 = (blockIdx.x % HB_) * ROWS;

    const float* srb = sr + (size_t)b * C_ * HW_;
    const float* hrb = hr + (size_t)b * C_ * HW_;

    // Zero the left/right padding columns (cols 0 and W+1 = 513)
    if (tid < 2 * TROWS) {
        int tr  = tid >> 1;
        int col = (tid & 1) ? (W_ + 1) : 0;
        g[tr * STR + col] = 0.0f;
    }

    // Load halo'd gray-diff tile: 34 rows x 128 float4-chunks = 4352 tasks, 17/thread
    #pragma unroll
    for (int it = 0; it < (TROWS * (W_ / 4)) / TPB; ++it) {
        int idx   = tid + it * TPB;
        int tr    = idx >> 7;          // / 128
        int chunk = idx & 127;
        int gr    = r0 + tr - 1;

        float4 d = make_float4(0.f, 0.f, 0.f, 0.f);
        if (gr >= 0 && gr < H_) {
            size_t off = (size_t)gr * W_ + chunk * 4;
            float4 s0 = *(const float4*)(srb + 0 * HW_ + off);
            float4 s1 = *(const float4*)(srb + 1 * HW_ + off);
            float4 s2 = *(const float4*)(srb + 2 * HW_ + off);
            float4 h0 = *(const float4*)(hrb + 0 * HW_ + off);
            float4 h1 = *(const float4*)(hrb + 1 * HW_ + off);
            float4 h2 = *(const float4*)(hrb + 2 * HW_ + off);
            d.x = 0.2989f * (s0.x - h0.x) + 0.587f * (s1.x - h1.x) + 0.114f * (s2.x - h2.x);
            d.y = 0.2989f * (s0.y - h0.y) + 0.587f * (s1.y - h1.y) + 0.114f * (s2.y - h2.y);
            d.z = 0.2989f * (s0.z - h0.z) + 0.587f * (s1.z - h1.z) + 0.114f * (s2.z - h2.z);
            d.w = 0.2989f * (s0.w - h0.w) + 0.587f * (s1.w - h1.w) + 0.114f * (s2.w - h2.w);
        }
        float* dst = g + tr * STR + 1 + chunk * 4;
        dst[0] = d.x; dst[1] = d.y; dst[2] = d.z; dst[3] = d.w;
    }
    __syncthreads();

    // Sobel + abs + accumulate: 32 rows x 512 cols = 16384 pixels, 64/thread
    float acc = 0.0f;
    #pragma unroll 4
    for (int it = 0; it < (ROWS * W_) / TPB; ++it) {
        int idx = tid + it * TPB;
        int rr  = idx >> 9;            // / 512  -> 0..31
        int c   = idx & 511;
        const float* p = g + rr * STR + c;   // top-left of 3x3 neighborhood
        float a00 = p[0],           a01 = p[1],           a02 = p[2];
        float a10 = p[STR],                               a12 = p[STR + 2];
        float a20 = p[2 * STR],     a21 = p[2 * STR + 1], a22 = p[2 * STR + 2];
        float gx = (a00 - a02) + 2.0f * (a10 - a12) + (a20 - a22);
        float gy = (a00 - a20) + 2.0f * (a01 - a21) + (a02 - a22);
        acc += fabsf(gx) + fabsf(gy);
    }

    // Block reduce to one partial
    #pragma unroll
    for (int off = 16; off > 0; off >>= 1)
        acc += __shfl_xor_sync(0xFFFFFFFFu, acc, off);

    __shared__ float wsum[TPB / 32];
    __shared__ bool s_last;
    if ((tid & 31) == 0) wsum[tid >> 5] = acc;
    __syncthreads();
    if (tid == 0) {
        float s = 0.0f;
        #pragma unroll
        for (int w = 0; w < TPB / 32; ++w) s += wsum[w];
        g_partials[blockIdx.x] = s;
        __threadfence();
        unsigned int prev = atomicAdd(&g_count, 1u);
        s_last = (prev == NBLK - 1);
    }
    __syncthreads();

    // Last block folds the final reduction (no second kernel launch)
    if (s_last) {
        double a = 0.0;
        for (int i = tid; i < NBLK; i += TPB) a += (double)g_partials[i];
        double* sd = (double*)g;   // reuse tile smem
        sd[tid] = a;
        __syncthreads();
        #pragma unroll
        for (int off = TPB / 2; off > 0; off >>= 1) {
            if (tid < off) sd[tid] += sd[tid + off];
            __syncthreads();
        }
        if (tid == 0) {
            out[0] = (float)(sd[0] / (double)(B_ * (size_t)HW_));
            g_count = 0;   // reset for next replay (deterministic)
        }
    }
}

extern "C" void kernel_launch(void* const* d_in, const int* in_sizes, int n_in,
                              void* d_out, int out_size)
{
    const float* sr = (const float*)d_in[0];
    const float* hr = (const float*)d_in[1];
    float* out = (float*)d_out;

    cudaFuncSetAttribute(edge_loss_kernel,
                         cudaFuncAttributeMaxDynamicSharedMemorySize, SMEM_BYTES);
    edge_loss_kernel<<<NBLK, TPB, SMEM_BYTES>>>(sr, hr, out);
}

// round 4
// speedup vs baseline: 1.1303x; 1.1296x over previous
#include <cuda_runtime.h>

#define B_   32
#define C_   3
#define H_   512
#define W_   512
#define HW_  (H_ * W_)
#define ROWS 16
#define HB_  (H_ / ROWS)          // 32 row-bands per image
#define NBLK (B_ * HB_)           // 1024 blocks
#define TPB  256
#define TROWS (ROWS + 2)          // 18 tile rows (with halo)
#define STR  516                  // smem row stride (W+2 padded to 516, %4==0)

__device__ float g_partials[NBLK];
__device__ unsigned int g_count = 0;

__global__ __launch_bounds__(TPB) void edge_loss_kernel(
    const float* __restrict__ sr, const float* __restrict__ hr,
    float* __restrict__ out)
{
    __shared__ float g[TROWS * STR];   // 37,152 B -> 6 CTAs/SM

    const int tid = threadIdx.x;
    const int b  = blockIdx.x / HB_;
    const int r0 = (blockIdx.x % HB_) * ROWS;

    const float* srb = sr + (size_t)b * C_ * HW_;
    const float* hrb = hr + (size_t)b * C_ * HW_;

    // Zero left/right padding columns (tile cols 0 and 513). Also zero col 514,515
    // (pad slack) so the float4 compute loads read defined memory.
    if (tid < 4 * TROWS) {
        int tr  = tid >> 2;
        int k   = tid & 3;
        int col = (k == 0) ? 0 : (W_ + k);   // 0, 513, 514, 515
        g[tr * STR + col] = 0.0f;
    }

    // Load halo'd gray-diff tile: 18 rows x 128 float4-chunks = 2304 tasks, 9/thread
    #pragma unroll
    for (int it = 0; it < (TROWS * (W_ / 4)) / TPB; ++it) {
        int idx   = tid + it * TPB;
        int tr    = idx >> 7;          // / 128
        int chunk = idx & 127;
        int gr    = r0 + tr - 1;

        float4 d = make_float4(0.f, 0.f, 0.f, 0.f);
        if (gr >= 0 && gr < H_) {
            size_t off = (size_t)gr * W_ + chunk * 4;
            float4 s0 = *(const float4*)(srb + 0 * HW_ + off);
            float4 s1 = *(const float4*)(srb + 1 * HW_ + off);
            float4 s2 = *(const float4*)(srb + 2 * HW_ + off);
            float4 h0 = *(const float4*)(hrb + 0 * HW_ + off);
            float4 h1 = *(const float4*)(hrb + 1 * HW_ + off);
            float4 h2 = *(const float4*)(hrb + 2 * HW_ + off);
            d.x = 0.2989f * (s0.x - h0.x) + 0.587f * (s1.x - h1.x) + 0.114f * (s2.x - h2.x);
            d.y = 0.2989f * (s0.y - h0.y) + 0.587f * (s1.y - h1.y) + 0.114f * (s2.y - h2.y);
            d.z = 0.2989f * (s0.z - h0.z) + 0.587f * (s1.z - h1.z) + 0.114f * (s2.z - h2.z);
            d.w = 0.2989f * (s0.w - h0.w) + 0.587f * (s1.w - h1.w) + 0.114f * (s2.w - h2.w);
        }
        float* dst = g + tr * STR + 1 + chunk * 4;
        dst[0] = d.x; dst[1] = d.y; dst[2] = d.z; dst[3] = d.w;
    }
    __syncthreads();

    // Sobel + abs + accumulate, 4 pixels per thread per step via LDS.128.
    // Pixel group (rr, c4..c4+3) needs tile cols c4..c4+5 of rows rr..rr+2
    // (data stored shifted +1, so base index rr*STR + c4 is the left neighbor).
    // 16 rows x 128 groups = 2048 groups, 8 iterations of 256 threads.
    float acc = 0.0f;
    #pragma unroll
    for (int it = 0; it < (ROWS * (W_ / 4)) / TPB; ++it) {
        int idx = tid + it * TPB;
        int rr  = idx >> 7;            // 0..15
        int c4  = (idx & 127) * 4;     // 0,4,...,508
        const float* p = g + rr * STR + c4;   // 16B-aligned

        float4 t0 = *(const float4*)(p);
        float4 t1 = *(const float4*)(p + 4);
        float4 m0 = *(const float4*)(p + STR);
        float4 m1 = *(const float4*)(p + STR + 4);
        float4 b0 = *(const float4*)(p + 2 * STR);
        float4 b1 = *(const float4*)(p + 2 * STR + 4);

        // top row values t[0..5] = t0.x t0.y t0.z t0.w t1.x t1.y  (etc.)
        // pixel j (j=0..3): gx = (t[j]-t[j+2]) + 2(m[j]-m[j+2]) + (b[j]-b[j+2])
        //                   gy = (t[j]-b[j]) + 2(t[j+1]-b[j+1]) + (t[j+2]-b[j+2])
        {
            float gx = (t0.x - t0.z) + 2.0f * (m0.x - m0.z) + (b0.x - b0.z);
            float gy = (t0.x - b0.x) + 2.0f * (t0.y - b0.y) + (t0.z - b0.z);
            acc += fabsf(gx) + fabsf(gy);
        }
        {
            float gx = (t0.y - t0.w) + 2.0f * (m0.y - m0.w) + (b0.y - b0.w);
            float gy = (t0.y - b0.y) + 2.0f * (t0.z - b0.z) + (t0.w - b0.w);
            acc += fabsf(gx) + fabsf(gy);
        }
        {
            float gx = (t0.z - t1.x) + 2.0f * (m0.z - m1.x) + (b0.z - b1.x);
            float gy = (t0.z - b0.z) + 2.0f * (t0.w - b0.w) + (t1.x - b1.x);
            acc += fabsf(gx) + fabsf(gy);
        }
        {
            float gx = (t0.w - t1.y) + 2.0f * (m0.w - m1.y) + (b0.w - b1.y);
            float gy = (t0.w - b0.w) + 2.0f * (t1.x - b1.x) + (t1.y - b1.y);
            acc += fabsf(gx) + fabsf(gy);
        }
    }

    // Block reduce to one partial
    #pragma unroll
    for (int off = 16; off > 0; off >>= 1)
        acc += __shfl_xor_sync(0xFFFFFFFFu, acc, off);

    __shared__ float wsum[TPB / 32];
    __shared__ bool s_last;
    if ((tid & 31) == 0) wsum[tid >> 5] = acc;
    __syncthreads();
    if (tid == 0) {
        float s = 0.0f;
        #pragma unroll
        for (int w = 0; w < TPB / 32; ++w) s += wsum[w];
        g_partials[blockIdx.x] = s;
        __threadfence();
        unsigned int prev = atomicAdd(&g_count, 1u);
        s_last = (prev == NBLK - 1);
    }
    __syncthreads();

    // Last block folds the final reduction (no second kernel launch)
    if (s_last) {
        double a = 0.0;
        for (int i = tid; i < NBLK; i += TPB) a += (double)g_partials[i];
        double* sd = (double*)g;   // reuse tile smem
        sd[tid] = a;
        __syncthreads();
        #pragma unroll
        for (int off = TPB / 2; off > 0; off >>= 1) {
            if (tid < off) sd[tid] += sd[tid + off];
            __syncthreads();
        }
        if (tid == 0) {
            out[0] = (float)(sd[0] / (double)(B_ * (size_t)HW_));
            g_count = 0;   // reset for next replay (deterministic)
        }
    }
}

extern "C" void kernel_launch(void* const* d_in, const int* in_sizes, int n_in,
                              void* d_out, int out_size)
{
    const float* sr = (const float*)d_in[0];
    const float* hr = (const float*)d_in[1];
    float* out = (float*)d_out;

    edge_loss_kernel<<<NBLK, TPB>>>(sr, hr, out);
}